// round 2
// baseline (speedup 1.0000x reference)
#include <cuda_runtime.h>
#include <math.h>

#define Hs 512
#define Ws 512
#define Bn 128
#define NSEG 363           // bins.max()+1 = round(256*sqrt(2)) + 1
#define TR 8               // tile rows
#define TC 16              // tile cols
#define TILES_X (Ws / TC)  // 32
#define TILES_Y (Hs / TR)  // 64
#define NTILES (TILES_X * TILES_Y)  // 2048
#define WIN 20             // ring window per tile (diag 16.55 + rounding slack)
#define PITCH 130          // even pitch: bank = (2*px + b) % 32, conflict-free both phases

// Global scratch (static device arrays — no allocation)
__device__ float g_S1[NSEG * Bn];
__device__ float g_S2[NSEG * Bn];
__device__ float g_cnt[NSEG];

// ---------------------------------------------------------------------------
__global__ void zero_kernel() {
    int i = blockIdx.x * blockDim.x + threadIdx.x;
    if (i < NSEG * Bn) { g_S1[i] = 0.f; g_S2[i] = 0.f; }
    if (i < NSEG) g_cnt[i] = 0.f;
}

// ---------------------------------------------------------------------------
// Per-ring pixel counts (batch independent): 262144 elements, trivial cost
// ---------------------------------------------------------------------------
__global__ void count_kernel(const int* __restrict__ bins) {
    __shared__ int c[NSEG];
    for (int i = threadIdx.x; i < NSEG; i += blockDim.x) c[i] = 0;
    __syncthreads();
    int idx = blockIdx.x * blockDim.x + threadIdx.x;
    int stride = gridDim.x * blockDim.x;
    for (; idx < Hs * Ws; idx += stride) {
        int r = bins[idx];
        if (r >= 0 && r < NSEG) atomicAdd(&c[r], 1);
    }
    __syncthreads();
    for (int i = threadIdx.x; i < NSEG; i += blockDim.x)
        if (c[i]) atomicAdd(&g_cnt[i], (float)c[i]);
}

// ---------------------------------------------------------------------------
// Pass 1: streaming segmented stats.
//   Block = one 8x16 pixel tile, ALL 128 batches. Thread t owns batch t.
//   acc[ringWindow][128]: column t written only by thread t -> no atomics.
//   Ring-change flush is warp-uniform (same pixel walk for every batch lane).
//   37.2 KB static smem -> 5 CTAs/SM for DRAM-latency hiding.
// ---------------------------------------------------------------------------
__global__ __launch_bounds__(128, 5) void pass1_kernel(
    const float* __restrict__ parts, const float* __restrict__ projs,
    const int* __restrict__ bins) {
    __shared__ float2 acc[WIN * Bn];            // 20480 B
    __shared__ float  nbuf[2 * TC * PITCH];     // 16640 B
    __shared__ int    rbuf[2 * TC];             // 128 B

    const int t = threadIdx.x;            // t == batch index
    const int tile = blockIdx.x;
    const int ty = tile / TILES_X, tx = tile % TILES_X;
    const int i0 = ty * TR, j0 = tx * TC;

    // Exact lower bound of ring index over the tile rect (center = (256,256)).
    float dI = (i0 > 256) ? (float)(i0 - 256)
             : ((i0 + TR - 1) < 256 ? (float)(256 - (i0 + TR - 1)) : 0.f);
    float dJ = (j0 > 256) ? (float)(j0 - 256)
             : ((j0 + TC - 1) < 256 ? (float)(256 - (j0 + TC - 1)) : 0.f);
    const int rbase = (int)floorf(sqrtf(dI * dI + dJ * dJ));

    #pragma unroll
    for (int k = 0; k < WIN; ++k) acc[k * Bn + t] = make_float2(0.f, 0.f);

    const int sub = t & 3;   // float4 slot along px (px0 = sub*4)
    const int bg  = t >> 2;  // batch-group 0..31
    float4 rp[4], rq[4];

    auto ldstage = [&](int s) {
        const int rowoff = (i0 + s) * Ws + j0 + sub * 4;
        #pragma unroll
        for (int r = 0; r < 4; ++r) {
            int b = r * 32 + bg;
            rp[r] = __ldcs((const float4*)(parts + (size_t)b * (Hs * Ws) + rowoff));
            rq[r] = __ldcs((const float4*)(projs + (size_t)b * (Hs * Ws) + rowoff));
        }
    };

    ldstage(0);
    float s1 = 0.f, s2 = 0.f;
    int cur = -1;

    for (int s = 0; s < TR; ++s) {
        const int bsel = s & 1;
        float* nb = nbuf + bsel * (TC * PITCH);
        int*   rb = rbuf + bsel * TC;
        __syncthreads();  // compute(s-2) done reading this buffer
        // Transposed store of noise = parts - projs (conflict-free, pitch 130)
        #pragma unroll
        for (int r = 0; r < 4; ++r) {
            int b = r * 32 + bg;
            float4 p = rp[r], q = rq[r];
            int px = sub * 4;
            nb[(px + 0) * PITCH + b] = p.x - q.x;
            nb[(px + 1) * PITCH + b] = p.y - q.y;
            nb[(px + 2) * PITCH + b] = p.z - q.z;
            nb[(px + 3) * PITCH + b] = p.w - q.w;
        }
        if (t < TC) rb[t] = bins[(i0 + s) * Ws + j0 + t];
        if (s + 1 < TR) ldstage(s + 1);  // prefetch next stage (MLP)
        __syncthreads();
        // Compute: thread t = batch t walks the 16 pixels of this row
        #pragma unroll 4
        for (int px = 0; px < TC; ++px) {
            float d = nb[px * PITCH + t];
            int r = rb[px];
            if (r != cur) {  // warp-uniform branch
                if (cur >= 0) {
                    int w = cur - rbase;
                    float2 a = acc[w * Bn + t];
                    a.x += s1; a.y += s2;
                    acc[w * Bn + t] = a;
                }
                cur = r; s1 = 0.f; s2 = 0.f;
            }
            s1 += fabsf(d);
            s2 = fmaf(d, d, s2);
        }
    }
    if (cur >= 0) {
        int w = cur - rbase;
        float2 a = acc[w * Bn + t];
        a.x += s1; a.y += s2;
        acc[w * Bn + t] = a;
    }
    // Merge the tile window into global scratch (spread REDG, cheap)
    #pragma unroll
    for (int w = 0; w < WIN; ++w) {
        int ring = rbase + w;
        if (ring >= NSEG) break;
        float2 a = acc[w * Bn + t];
        if (a.x != 0.f || a.y != 0.f) {
            atomicAdd(&g_S1[ring * Bn + t], a.x);
            atomicAdd(&g_S2[ring * Bn + t], a.y);
        }
    }
}

// ---------------------------------------------------------------------------
// Pass 2: per-(batch, ring 4..255) closed-form contribution; warp per batch.
//   logprob[b] = sum_r [ -0.5*S2/var - c*log(2*pi*var) ]
//   with var = (S2 - c*mean^2)/max(c-1,1), mean = S1/max(c,1).
// ---------------------------------------------------------------------------
__global__ void pass3_kernel(float* __restrict__ out) {
    int b = blockIdx.x * 8 + (threadIdx.x >> 5);  // 16 blocks x 8 warps
    int lane = threadIdx.x & 31;
    float sum = 0.f;
    for (int r = 4 + lane; r < 256; r += 32) {
        float c   = g_cnt[r];
        float s1v = g_S1[r * Bn + b];
        float s2v = g_S2[r * Bn + b];
        float mean = s1v / fmaxf(c, 1.f);
        float ssq  = s2v - c * mean * mean;
        float var  = ssq / fmaxf(c - 1.f, 1.f);
        sum += -0.5f * s2v / var - c * logf(6.283185307179586f * var);
    }
    #pragma unroll
    for (int off = 16; off > 0; off >>= 1)
        sum += __shfl_xor_sync(0xFFFFFFFFu, sum, off);
    if (lane == 0) out[b] = sum;
}

// ---------------------------------------------------------------------------
extern "C" void kernel_launch(void* const* d_in, const int* in_sizes, int n_in,
                              void* d_out, int out_size) {
    const float* parts = (const float*)d_in[0];
    const float* projs = (const float*)d_in[1];
    const int*   bins  = (const int*)d_in[2];
    // d_in[3] (valid_mask) unused: mask == (3 < bin < 256), folded analytically.
    float* out = (float*)d_out;

    zero_kernel<<<(NSEG * Bn + 255) / 256, 256>>>();
    count_kernel<<<128, 256>>>(bins);
    pass1_kernel<<<NTILES, 128>>>(parts, projs, bins);
    pass3_kernel<<<16, 256>>>(out);
}

// round 3
// speedup vs baseline: 1.3725x; 1.3725x over previous
#include <cuda_runtime.h>
#include <math.h>

#define Hs 512
#define Ws 512
#define Bn 128
#define NSEG 363           // bins.max()+1
#define NRING 256          // only rings 4..255 matter for the output
#define PAIRS 128          // ring pairs 0..127 (rings 0..255)
#define TR 8               // tile rows
#define TC 32              // tile cols
#define TILES_X (Ws / TC)  // 16
#define TILES_Y (Hs / TR)  // 64
#define NTILES (TILES_X * TILES_Y)  // 1024
#define WIN 36             // even-aligned ring window (span <= 35 incl. parity pad)
#define PITCH 129          // transpose staging pitch (conflict-free both phases)

// Global scratch (static device arrays — no allocation).
// g_S4[b*PAIRS + p] = (S1[2p], S2[2p], S1[2p+1], S2[2p+1]) for batch b.
__device__ float4 g_S4[Bn * PAIRS];
__device__ float  g_cnt[NRING];

// ---------------------------------------------------------------------------
__global__ void zero_kernel() {
    int i = blockIdx.x * blockDim.x + threadIdx.x;
    if (i < Bn * PAIRS) g_S4[i] = make_float4(0.f, 0.f, 0.f, 0.f);
    if (i < NRING) g_cnt[i] = 0.f;
}

// ---------------------------------------------------------------------------
// Per-ring pixel counts (batch independent); only rings 4..255 needed.
// ---------------------------------------------------------------------------
__global__ void count_kernel(const int* __restrict__ bins) {
    __shared__ int c[NRING];
    for (int i = threadIdx.x; i < NRING; i += blockDim.x) c[i] = 0;
    __syncthreads();
    int idx = blockIdx.x * blockDim.x + threadIdx.x;
    int stride = gridDim.x * blockDim.x;
    for (; idx < Hs * Ws; idx += stride) {
        int r = bins[idx];
        if (r > 3 && r < NRING) atomicAdd(&c[r], 1);
    }
    __syncthreads();
    for (int i = threadIdx.x; i < NRING; i += blockDim.x)
        if (c[i]) atomicAdd(&g_cnt[i], (float)c[i]);
}

// ---------------------------------------------------------------------------
// Pass 1: streaming segmented stats.
//   Block = one 8x32 tile, ALL 128 batches. Thread t owns batch t.
//   acc[win][128] in smem: column t written only by thread t -> no atomics.
//   Ring-change flush is warp-uniform. Merge = packed float4 REDG (2 rings/op).
//   Tiles fully outside r=256 are skipped (never affect the output).
// ---------------------------------------------------------------------------
__global__ __launch_bounds__(128, 3) void pass1_kernel(
    const float* __restrict__ parts, const float* __restrict__ projs,
    const int* __restrict__ bins) {
    extern __shared__ char smraw[];
    float2* acc  = (float2*)smraw;                                   // WIN*128 float2
    float*  nbuf = (float*)(smraw + WIN * Bn * sizeof(float2));      // 2*TC*PITCH floats
    int*    rbuf = (int*)(smraw + WIN * Bn * sizeof(float2)
                                + 2 * TC * PITCH * sizeof(float));   // 2*TC ints

    const int t = threadIdx.x;            // t == batch index
    const int tile = blockIdx.x;
    const int ty = tile / TILES_X, tx = tile % TILES_X;
    const int i0 = ty * TR, j0 = tx * TC;

    // Exact lower bound of ring index over the tile rect (center = (256,256)).
    float dI = (i0 > 256) ? (float)(i0 - 256)
             : ((i0 + TR - 1) < 256 ? (float)(256 - (i0 + TR - 1)) : 0.f);
    float dJ = (j0 > 256) ? (float)(j0 - 256)
             : ((j0 + TC - 1) < 256 ? (float)(256 - (j0 + TC - 1)) : 0.f);
    const int rbase = (int)floorf(sqrtf(dI * dI + dJ * dJ));
    if (rbase >= NRING) return;           // tile entirely irrelevant to output
    const int rbase2 = rbase & ~1;        // even-aligned window base

    #pragma unroll
    for (int k = 0; k < WIN; ++k) acc[k * Bn + t] = make_float2(0.f, 0.f);

    const int sub = t & 7;   // float4 slot along px (px0 = sub*4)
    const int bg  = t >> 3;  // batch-group 0..15
    float4 rp[8], rq[8];

    auto ldstage = [&](int s) {
        const int rowoff = (i0 + s) * Ws + j0 + sub * 4;
        #pragma unroll
        for (int r = 0; r < 8; ++r) {
            int b = r * 16 + bg;
            rp[r] = __ldcs((const float4*)(parts + (size_t)b * (Hs * Ws) + rowoff));
            rq[r] = __ldcs((const float4*)(projs + (size_t)b * (Hs * Ws) + rowoff));
        }
    };

    ldstage(0);
    float s1 = 0.f, s2 = 0.f;
    int cur = -1;

    for (int s = 0; s < TR; ++s) {
        const int bsel = s & 1;
        float* nb = nbuf + bsel * (TC * PITCH);
        int*   rb = rbuf + bsel * TC;
        __syncthreads();  // compute(s-2) done reading this buffer
        // Transposed store of noise = parts - projs (conflict-free, pitch 129)
        #pragma unroll
        for (int r = 0; r < 8; ++r) {
            int b = r * 16 + bg;
            float4 p = rp[r], q = rq[r];
            int px = sub * 4;
            nb[(px + 0) * PITCH + b] = p.x - q.x;
            nb[(px + 1) * PITCH + b] = p.y - q.y;
            nb[(px + 2) * PITCH + b] = p.z - q.z;
            nb[(px + 3) * PITCH + b] = p.w - q.w;
        }
        if (t < TC) rb[t] = bins[(i0 + s) * Ws + j0 + t];
        if (s + 1 < TR) ldstage(s + 1);  // prefetch next stage (MLP)
        __syncthreads();
        // Compute: thread t = batch t walks the 32 pixels of this row
        #pragma unroll 4
        for (int px = 0; px < TC; ++px) {
            float d = nb[px * PITCH + t];
            int r = rb[px];
            if (r != cur) {  // warp-uniform branch
                if (cur >= 0) {
                    int w = cur - rbase2;
                    float2 a = acc[w * Bn + t];
                    a.x += s1; a.y += s2;
                    acc[w * Bn + t] = a;
                }
                cur = r; s1 = 0.f; s2 = 0.f;
            }
            s1 += fabsf(d);
            s2 = fmaf(d, d, s2);
        }
    }
    if (cur >= 0) {
        int w = cur - rbase2;
        float2 a = acc[w * Bn + t];
        a.x += s1; a.y += s2;
        acc[w * Bn + t] = a;
    }
    // Merge: packed vector reduction, two rings per red.global.add.v4.f32.
    // Only rings in [4, 256) can affect the output.
    const int p0 = (rbase2 > 4) ? rbase2 : 4;                    // even
    const int p1 = (rbase2 + WIN < NRING) ? rbase2 + WIN : NRING; // exclusive
    for (int ring = p0; ring < p1; ring += 2) {
        int w = ring - rbase2;
        float2 a0 = acc[w * Bn + t];
        float2 a1 = acc[(w + 1) * Bn + t];
        if (a0.x != 0.f || a1.x != 0.f) {
            float4* ptr = &g_S4[t * PAIRS + (ring >> 1)];
            asm volatile("red.global.add.v4.f32 [%0], {%1, %2, %3, %4};"
                         :: "l"(ptr), "f"(a0.x), "f"(a0.y), "f"(a1.x), "f"(a1.y)
                         : "memory");
        }
    }
}

// ---------------------------------------------------------------------------
// Pass 2: per-(batch, ring 4..255) closed-form contribution; warp per batch.
//   logprob[b] = sum_r [ -0.5*S2/var - c*log(2*pi*var) ]
//   with var = (S2 - c*mean^2)/max(c-1,1), mean = S1/max(c,1).
// ---------------------------------------------------------------------------
__global__ void pass3_kernel(float* __restrict__ out) {
    int b = blockIdx.x;
    int lane = threadIdx.x & 31;
    float sum = 0.f;
    for (int p = 2 + lane; p < PAIRS; p += 32) {   // pairs 2..127 = rings 4..255
        float4 v = g_S4[b * PAIRS + p];
        #pragma unroll
        for (int h = 0; h < 2; ++h) {
            float c   = g_cnt[2 * p + h];
            float s1v = h ? v.z : v.x;
            float s2v = h ? v.w : v.y;
            float mean = s1v / fmaxf(c, 1.f);
            float ssq  = s2v - c * mean * mean;
            float var  = ssq / fmaxf(c - 1.f, 1.f);
            sum += -0.5f * s2v / var - c * logf(6.283185307179586f * var);
        }
    }
    #pragma unroll
    for (int off = 16; off > 0; off >>= 1)
        sum += __shfl_xor_sync(0xFFFFFFFFu, sum, off);
    if (lane == 0) out[b] = sum;
}

// ---------------------------------------------------------------------------
extern "C" void kernel_launch(void* const* d_in, const int* in_sizes, int n_in,
                              void* d_out, int out_size) {
    const float* parts = (const float*)d_in[0];
    const float* projs = (const float*)d_in[1];
    const int*   bins  = (const int*)d_in[2];
    // d_in[3] (valid_mask) unused: mask == (3 < bin < 256), folded analytically.
    float* out = (float*)d_out;

    const int smem = WIN * Bn * (int)sizeof(float2)
                   + 2 * TC * PITCH * (int)sizeof(float)
                   + 2 * TC * (int)sizeof(int);  // 70144 B
    cudaFuncSetAttribute(pass1_kernel,
                         cudaFuncAttributeMaxDynamicSharedMemorySize, smem);

    zero_kernel<<<(Bn * PAIRS + 255) / 256, 256>>>();
    count_kernel<<<128, 256>>>(bins);
    pass1_kernel<<<NTILES, 128, smem>>>(parts, projs, bins);
    pass3_kernel<<<Bn, 32>>>(out);
}